// round 17
// baseline (speedup 1.0000x reference)
#include <cuda_runtime.h>
#include <cstdint>

#define Bsz 8
#define Nn 2048
#define FIN 128
#define FO 64
#define ALPHA 0.2f

#define BM 32
#define BN 32
#define NZ 2                       // j-split factor
#define NTILES (Nn / BN / NZ)      // 32 tiles per CTA
#define NS 3                       // cp.async pipeline stages
#define PPITCH 258                 // sP group pitch (words): ≡2 mod 8 → CF LDS.64

// Scratch device globals (allocation-free per harness rules)
__device__ float g_Wh[Bsz * Nn * FO];        // ROW-major: [b*N+n][o]
__device__ float g_e1[Bsz * Nn];
__device__ float g_e2[Bsz * Nn];
__device__ float g_pN[NZ][Bsz * Nn * FO];    // partial numerators
__device__ float g_pS[NZ][Bsz * Nn];         // partial row sums

// ---------------------------------------------------------------------------
// helpers
// ---------------------------------------------------------------------------
static __device__ __forceinline__ uint32_t smem_u32(const void* p) {
    uint32_t a;
    asm("{ .reg .u64 t; cvta.to.shared.u64 t, %1; cvt.u32.u64 %0, t; }"
        : "=r"(a) : "l"(p));
    return a;
}
static __device__ __forceinline__ void cp16(uint32_t dst, const void* src) {
    asm volatile("cp.async.cg.shared.global [%0], [%1], 16;"
                 :: "r"(dst), "l"(src) : "memory");
}
#define CP_COMMIT() asm volatile("cp.async.commit_group;" ::: "memory")
#define CP_WAIT1()  asm volatile("cp.async.wait_group 1;" ::: "memory")

static __device__ __forceinline__ float tf32r(float x) {
    uint32_t u;
    asm("cvt.rna.tf32.f32 %0, %1;" : "=r"(u) : "f"(x));
    return __uint_as_float(u);
}
static __device__ __forceinline__ uint32_t tf32b(float x) {
    uint32_t u;
    asm("cvt.rna.tf32.f32 %0, %1;" : "=r"(u) : "f"(x));
    return u;
}

static __device__ __forceinline__ void mma_tf32(
    float* d, uint32_t a0, uint32_t a1, uint32_t a2, uint32_t a3,
    uint32_t b0, uint32_t b1)
{
    asm volatile(
        "mma.sync.aligned.m16n8k8.row.col.f32.tf32.tf32.f32 "
        "{%0,%1,%2,%3},{%4,%5,%6,%7},{%8,%9},{%0,%1,%2,%3};"
        : "+f"(d[0]), "+f"(d[1]), "+f"(d[2]), "+f"(d[3])
        : "r"(a0), "r"(a1), "r"(a2), "r"(a3), "r"(b0), "r"(b1));
}

// ---------------------------------------------------------------------------
// Kernel 1 (v2): Wh = h @ W via 3xTF32 mma (fp32-accurate); e1/e2 fused.
// 256 blocks x 256 threads; 64 rows/block; warp tile 32 rows x 16 cols.
// K chunked 2x64 through smem. Wh written ROW-major directly from registers.
// ---------------------------------------------------------------------------
__global__ __launch_bounds__(256) void gat_proj_kernel(
    const float* __restrict__ h,
    const float* __restrict__ W,
    const float* __restrict__ a)
{
    __shared__ __align__(16) float sH[64 * 64];      // 16 KB, additive swizzle
    __shared__ __align__(16) float sWs[64 * 64];     // 16 KB, o-major XOR swizzle
    __shared__ float sE1p[4][64], sE2p[4][64];       // per-wn partials
    __shared__ float sA1[FO], sA2[FO];

    const int t = threadIdx.x;
    const int warp = t >> 5, lane = t & 31;
    const int wm = warp & 1, wn = warp >> 1;          // wm: 32-row half; wn: 16-col group
    const int lq = lane >> 2, lr = lane & 3;
    const int g0 = blockIdx.x * 64;

    if (t < FO) { sA1[t] = a[t]; sA2[t] = a[FO + t]; }

    float acc[2][2][4];
#pragma unroll
    for (int m = 0; m < 2; m++)
#pragma unroll
        for (int n = 0; n < 2; n++)
#pragma unroll
            for (int r = 0; r < 4; r++) acc[m][n][r] = 0.f;

    const int hrow = t >> 2;          // sH load: row
    const int hk   = (t & 3) * 16;    // sH load: k base
    const int wo   = t & 63;          // sW transpose: o
    const int wg   = (t >> 6) * 16;   // sW transpose: k base

    for (int kc = 0; kc < 2; kc++) {
        __syncthreads();   // protect previous chunk's readers
        // stage h chunk [64 rows x 64 k], word = (i<<6) + ((k + 4i)&63)
#pragma unroll
        for (int cc = 0; cc < 4; cc++) {
            const int k0 = hk + cc * 4;
            *(float4*)&sH[(hrow << 6) + ((k0 + 4 * hrow) & 63)] =
                *(const float4*)&h[(long)(g0 + hrow) * FIN + kc * 64 + k0];
        }
        // stage W chunk transposed [64 o x 64 k], word = (o<<6) + (k ^ 4(o&7))
#pragma unroll
        for (int j = 0; j < 16; j++) {
            const int kl = wg + j;
            sWs[(wo << 6) + (kl ^ ((wo & 7) << 2))] =
                W[(long)(kc * 64 + kl) * FO + wo];
        }
        __syncthreads();

#pragma unroll
        for (int k8 = 0; k8 < 8; k8++) {
            const int c0 = k8 * 8 + lr;
            uint32_t Ah[2][4], Al[2][4];
#pragma unroll
            for (int m = 0; m < 2; m++) {
                const int r0 = wm * 32 + m * 16 + lq, r1 = r0 + 8;
                const float v0 = sH[(r0 << 6) + ((c0     + 4 * r0) & 63)];
                const float v1 = sH[(r1 << 6) + ((c0     + 4 * r1) & 63)];
                const float v2 = sH[(r0 << 6) + ((c0 + 4 + 4 * r0) & 63)];
                const float v3 = sH[(r1 << 6) + ((c0 + 4 + 4 * r1) & 63)];
                Ah[m][0] = tf32b(v0); Al[m][0] = tf32b(v0 - __uint_as_float(Ah[m][0]));
                Ah[m][1] = tf32b(v1); Al[m][1] = tf32b(v1 - __uint_as_float(Ah[m][1]));
                Ah[m][2] = tf32b(v2); Al[m][2] = tf32b(v2 - __uint_as_float(Ah[m][2]));
                Ah[m][3] = tf32b(v3); Al[m][3] = tf32b(v3 - __uint_as_float(Ah[m][3]));
            }
            uint32_t Bh[2][2], Bl[2][2];
#pragma unroll
            for (int n = 0; n < 2; n++) {
                const int o = wn * 16 + n * 8 + lq;
                const int sw = (o & 7) << 2;
                const float w0 = sWs[(o << 6) + ((k8 * 8 + lr)     ^ sw)];
                const float w1 = sWs[(o << 6) + ((k8 * 8 + lr + 4) ^ sw)];
                Bh[n][0] = tf32b(w0); Bl[n][0] = tf32b(w0 - __uint_as_float(Bh[n][0]));
                Bh[n][1] = tf32b(w1); Bl[n][1] = tf32b(w1 - __uint_as_float(Bh[n][1]));
            }
#pragma unroll
            for (int m = 0; m < 2; m++)
#pragma unroll
                for (int n = 0; n < 2; n++) {
                    mma_tf32(acc[m][n], Ah[m][0], Ah[m][1], Ah[m][2], Ah[m][3],
                             Bh[n][0], Bh[n][1]);
                    mma_tf32(acc[m][n], Ah[m][0], Ah[m][1], Ah[m][2], Ah[m][3],
                             Bl[n][0], Bl[n][1]);
                    mma_tf32(acc[m][n], Al[m][0], Al[m][1], Al[m][2], Al[m][3],
                             Bh[n][0], Bh[n][1]);
                }
        }
    }

    // ---- e1/e2 partials (deterministic: shfl over lr, then per-wn slots) ----
    float e1p[2][2] = {{0.f, 0.f}, {0.f, 0.f}};
    float e2p[2][2] = {{0.f, 0.f}, {0.f, 0.f}};
#pragma unroll
    for (int m = 0; m < 2; m++)
#pragma unroll
        for (int n = 0; n < 2; n++) {
            const int c0 = wn * 16 + n * 8 + lr * 2, c1 = c0 + 1;
            e1p[m][0] += acc[m][n][0] * sA1[c0] + acc[m][n][1] * sA1[c1];
            e1p[m][1] += acc[m][n][2] * sA1[c0] + acc[m][n][3] * sA1[c1];
            e2p[m][0] += acc[m][n][0] * sA2[c0] + acc[m][n][1] * sA2[c1];
            e2p[m][1] += acc[m][n][2] * sA2[c0] + acc[m][n][3] * sA2[c1];
        }
#pragma unroll
    for (int m = 0; m < 2; m++)
#pragma unroll
        for (int hf = 0; hf < 2; hf++) {
            e1p[m][hf] += __shfl_xor_sync(0xffffffffu, e1p[m][hf], 1);
            e1p[m][hf] += __shfl_xor_sync(0xffffffffu, e1p[m][hf], 2);
            e2p[m][hf] += __shfl_xor_sync(0xffffffffu, e2p[m][hf], 1);
            e2p[m][hf] += __shfl_xor_sync(0xffffffffu, e2p[m][hf], 2);
        }
    if (lr == 0) {
#pragma unroll
        for (int m = 0; m < 2; m++) {
            const int r = wm * 32 + m * 16 + lq;
            sE1p[wn][r]     = e1p[m][0];
            sE1p[wn][r + 8] = e1p[m][1];
            sE2p[wn][r]     = e2p[m][0];
            sE2p[wn][r + 8] = e2p[m][1];
        }
    }

    // ---- Wh store (row-major, straight from registers) ----
#pragma unroll
    for (int m = 0; m < 2; m++)
#pragma unroll
        for (int n = 0; n < 2; n++) {
            const int r0 = wm * 32 + m * 16 + lq;
            const int c0 = wn * 16 + n * 8 + lr * 2;
            *(float2*)&g_Wh[(long)(g0 + r0) * FO + c0] =
                make_float2(acc[m][n][0], acc[m][n][1]);
            *(float2*)&g_Wh[(long)(g0 + r0 + 8) * FO + c0] =
                make_float2(acc[m][n][2], acc[m][n][3]);
        }

    __syncthreads();
    if (t < 64) {
        g_e1[g0 + t] = (sE1p[0][t] + sE1p[1][t]) + (sE1p[2][t] + sE1p[3][t]);
        g_e2[g0 + t] = (sE2p[0][t] + sE2p[1][t]) + (sE2p[2][t] + sE2p[3][t]);
    }
}

// ---------------------------------------------------------------------------
// Kernel 2: PARTIAL masked-softmax aggregation via mma.sync tf32.
// grid (64, 8, 2) = 1024 CTAs, 256 threads. V staged j-major from row-major Wh
// (XOR mask 8*(j&7), cp16-compatible, B-fragments conflict-free).
// ---------------------------------------------------------------------------
__global__ __launch_bounds__(256, 4) void gat_agg_partial_kernel(
    const int* __restrict__ adj)
{
    __shared__ __align__(16) int   sAdj[NS][BM * BN];   // 12 KB
    __shared__ __align__(16) float sVT[NS][BN * FO];    // 24 KB (j-major, XOR)
    __shared__ __align__(16) float sP[2][4 * PPITCH];   // ~8.1 KB (grouped by c&3)

    const int b  = blockIdx.y;
    const int i0 = blockIdx.x * BM;
    const int zh = blockIdx.z;
    const int jz = zh * (Nn / NZ);
    const int t  = threadIdx.x;
    const int warp = t >> 5;
    const int lane = t & 31;

    // score mapping: thread <-> (row, 4 j's)
    const int rowi = t >> 3;
    const int jq   = (t & 7) * 4;
    const int qP   = jq >> 2;
    const float e1i = g_e1[b * Nn + i0 + rowi];
    const int*   adjRow = adj + ((long)(b * Nn + i0 + rowi)) * Nn + jz + jq;
    const float* e2p    = g_e2 + b * Nn + jz + jq;

    // V staging: thread <-> (j, 8 o's); source = row-major Wh
    const int vj = t >> 3;              // 0..31
    const int vo = (t & 7) * 8;         // 0..56
    const int vs = (vj & 7) << 3;       // XOR mask
    const float* vsrc = g_Wh + ((long)(b * Nn + jz + vj)) * FO + vo;

    // per-thread fixed smem dst addresses
    const uint32_t adjDst = smem_u32(&sAdj[0][0]) + (uint32_t)((rowi * BN + jq) * 4);
    const uint32_t vDst0  = smem_u32(&sVT[0][0]) + (uint32_t)(((vj << 6) + (vo ^ vs)) * 4);
    const uint32_t vDst1  = smem_u32(&sVT[0][0]) + (uint32_t)(((vj << 6) + ((vo + 4) ^ vs)) * 4);

    // matmul mapping: warp tile 16 rows x 16 cols
    const int wm = warp & 1;
    const int wn = warp >> 1;
    const int lq = lane >> 2;
    const int lr = lane & 3;
    const int r0 = wm * 16 + lq;
    const int r1 = r0 + 8;
    const int aOff0 = lr * PPITCH + r0 * 8;
    const int aOff1 = lr * PPITCH + r1 * 8;
    const int bm0 = lr << 3;            // b0 XOR mask
    const int bm1 = (lr << 3) ^ 32;     // b1 XOR mask

    float acc[2][4];
#pragma unroll
    for (int n = 0; n < 2; n++)
#pragma unroll
        for (int r = 0; r < 4; r++) acc[n][r] = 0.f;

    float ssum = 0.f;

    // ---- prologue: issue stages for tiles 0, 1 ----
#pragma unroll
    for (int s = 0; s < NS - 1; s++) {
        cp16(adjDst + (uint32_t)(s * BM * BN * 4), adjRow + s * BN);
        cp16(vDst0 + (uint32_t)(s * BN * FO * 4), vsrc + (long)s * BN * FO);
        cp16(vDst1 + (uint32_t)(s * BN * FO * 4), vsrc + (long)s * BN * FO + 4);
        CP_COMMIT();
    }
    float4 e2cur = *(const float4*)(e2p);

    int stg = 0;
    int stgI = NS - 1;

    for (int tile = 0; tile < NTILES; tile++) {
        const int buf = tile & 1;

        float4 e2nxt;
        if (tile < NTILES - 1) e2nxt = *(const float4*)(e2p + (tile + 1) * BN);

        CP_WAIT1();

        // ---- scores from own adj words; store into grouped sP layout ----
        {
            const int4 av = *(const int4*)&sAdj[stg][rowi * BN + jq];
            float p0, p1, p2, p3;
            float x;
            x = e1i + e2cur.x; x = fmaxf(x, ALPHA * x);
            p0 = (av.x > 0) ? tf32r(__expf(x)) : 0.f;
            x = e1i + e2cur.y; x = fmaxf(x, ALPHA * x);
            p1 = (av.y > 0) ? tf32r(__expf(x)) : 0.f;
            x = e1i + e2cur.z; x = fmaxf(x, ALPHA * x);
            p2 = (av.z > 0) ? tf32r(__expf(x)) : 0.f;
            x = e1i + e2cur.w; x = fmaxf(x, ALPHA * x);
            p3 = (av.w > 0) ? tf32r(__expf(x)) : 0.f;
            ssum += (p0 + p1) + (p2 + p3);
            float* pb = &sP[buf][rowi * 8 + qP];
            pb[0 * PPITCH] = p0;
            pb[1 * PPITCH] = p1;
            pb[2 * PPITCH] = p2;
            pb[3 * PPITCH] = p3;
        }
        e2cur = e2nxt;

        __syncthreads();

        // ---- issue loads for tile+NS-1 ----
        {
            const int jt = tile + NS - 1;
            if (jt < NTILES) {
                const uint32_t so  = (uint32_t)(stgI * BM * BN * 4);
                const uint32_t vso = (uint32_t)(stgI * BN * FO * 4);
                cp16(adjDst + so, adjRow + jt * BN);
                cp16(vDst0 + vso, vsrc + (long)jt * BN * FO);
                cp16(vDst1 + vso, vsrc + (long)jt * BN * FO + 4);
            }
            CP_COMMIT();
        }

        // ---- MMA: 4 k-steps x 2 n-tiles, m16n8k8 tf32 ----
        const float* cP = &sP[buf][0];
        const float* cV = &sVT[stg][0];
#pragma unroll
        for (int k = 0; k < 4; k++) {
            const float2 a02 = *(const float2*)&cP[aOff0 + 2 * k];
            const float2 a13 = *(const float2*)&cP[aOff1 + 2 * k];
            const int jb = k * 8 + lr;
#pragma unroll
            for (int nt = 0; nt < 2; nt++) {
                const int o = wn * 16 + nt * 8 + lq;
                const uint32_t b0 = __float_as_uint(cV[(jb << 6) + (o ^ bm0)]);
                const uint32_t b1 = __float_as_uint(cV[((jb + 4) << 6) + (o ^ bm1)]);
                mma_tf32(acc[nt],
                         __float_as_uint(a02.x), __float_as_uint(a13.x),
                         __float_as_uint(a02.y), __float_as_uint(a13.y),
                         b0, b1);
            }
        }

        stg  = (stg == NS - 1) ? 0 : stg + 1;
        stgI = (stgI == NS - 1) ? 0 : stgI + 1;
    }

    // ---- partial row sums ----
    ssum += __shfl_xor_sync(0xffffffffu, ssum, 1);
    ssum += __shfl_xor_sync(0xffffffffu, ssum, 2);
    ssum += __shfl_xor_sync(0xffffffffu, ssum, 4);
    if ((t & 7) == 0) g_pS[zh][b * Nn + i0 + rowi] = ssum;

    // ---- store raw partial numerators ----
    {
        float* o0 = &g_pN[zh][((long)(b * Nn + i0 + r0)) * FO];
        float* o1 = &g_pN[zh][((long)(b * Nn + i0 + r1)) * FO];
#pragma unroll
        for (int nt = 0; nt < 2; nt++) {
            const int col = wn * 16 + nt * 8 + lr * 2;
            *(float2*)(o0 + col) = make_float2(acc[nt][0], acc[nt][1]);
            *(float2*)(o1 + col) = make_float2(acc[nt][2], acc[nt][3]);
        }
    }
}

// ---------------------------------------------------------------------------
// Kernel 3: combine halves, normalize, ELU.
// ---------------------------------------------------------------------------
__global__ __launch_bounds__(256) void gat_combine_kernel(float* __restrict__ out)
{
    const int idx = blockIdx.x * 256 + threadIdx.x;
    const int row = idx >> 4;
    const int cq  = (idx & 15) * 4;

    float s = 0.f;
#pragma unroll
    for (int z = 0; z < NZ; z++) s += g_pS[z][row];
    const float inv = 1.0f / s;

    float4 n = *(const float4*)&g_pN[0][(long)row * FO + cq];
#pragma unroll
    for (int z = 1; z < NZ; z++) {
        const float4 nz = *(const float4*)&g_pN[z][(long)row * FO + cq];
        n.x += nz.x; n.y += nz.y; n.z += nz.z; n.w += nz.w;
    }

    float4 o;
    float x;
    x = n.x * inv; o.x = (x > 0.f) ? x : expm1f(x);
    x = n.y * inv; o.y = (x > 0.f) ? x : expm1f(x);
    x = n.z * inv; o.z = (x > 0.f) ? x : expm1f(x);
    x = n.w * inv; o.w = (x > 0.f) ? x : expm1f(x);
    *(float4*)&out[(long)row * FO + cq] = o;
}

// ---------------------------------------------------------------------------
extern "C" void kernel_launch(void* const* d_in, const int* in_sizes, int n_in,
                              void* d_out, int out_size)
{
    const float* h   = (const float*)d_in[0];
    const int*   adj = (const int*)d_in[1];
    const float* W   = (const float*)d_in[2];
    const float* a   = (const float*)d_in[3];
    float* out = (float*)d_out;

    gat_proj_kernel<<<(Bsz * Nn) / 64, 256>>>(h, W, a);
    gat_agg_partial_kernel<<<dim3(Nn / BM, Bsz, NZ), 256>>>(adj);
    gat_combine_kernel<<<(Bsz * Nn * FO / 4) / 256, 256>>>(out);
}